// round 5
// baseline (speedup 1.0000x reference)
#include <cuda_runtime.h>
#include <cuda_fp16.h>
#include <math.h>

#define Mdim 2048
#define Ndim 2048
#define MP   2049
#define NP   2049
#define Bdim 4
#define Ddim 256
#define Pdim 8
#define UST  2052   // padded stride for u/v (16B-aligned batch slices)

__device__ float g_u[Bdim * UST];
__device__ float g_v[Bdim * UST];
__device__ float g_dA[(size_t)Bdim * MP * Pdim];
__device__ float g_dB[(size_t)Bdim * MP * Pdim];
__device__ __half g_hR[(size_t)Bdim * Mdim * Ndim];  // half(S * log2e), row-major
__device__ __half g_hC[(size_t)Bdim * Mdim * Ndim];  // transposed copy

#define LOG2E_ 1.4426950408889634f
#define LN2_   0.6931471805599453f

// ---------------------------------------------------------------- utilities

__device__ __forceinline__ float ex2(float x) {
    float y;
    asm("ex2.approx.f32 %0, %1;" : "=f"(y) : "f"(x));
    return y;
}

__device__ __forceinline__ float warp_reduce_sum(float x) {
#pragma unroll
    for (int o = 16; o; o >>= 1) x += __shfl_xor_sync(0xffffffffu, x, o);
    return x;
}

__device__ __forceinline__ float gelu(float x) {
    return 0.5f * x * (1.0f + erff(x * 0.7071067811865476f));
}

// Branchless insert of x into sorted-descending t[5].
__device__ __forceinline__ void ladder5(float t[5], float x) {
#pragma unroll
    for (int i = 0; i < 5; i++) {
        float hi = fmaxf(t[i], x);
        x = fminf(t[i], x);
        t[i] = hi;
    }
}

__device__ __forceinline__ void merge5(float t[5], const float s[5]) {
#pragma unroll
    for (int i = 0; i < 5; i++) ladder5(t, s[i]);
}

__device__ __forceinline__ void top5_merge_shfl(float t[5]) {
#pragma unroll
    for (int o = 16; o; o >>= 1) {
        float p[5];
#pragma unroll
        for (int i = 0; i < 5; i++) p[i] = __shfl_xor_sync(0xffffffffu, t[i], o);
        merge5(t, p);
    }
}

// ---------------------------------------------------------------- MLP (warp-cooperative)

struct MlpW {
    float w1t[16 * 64];
    float b1[64], g1[64], be1[64];
    float w2t[64 * 64];
    float b2[64], g2[64], be2[64];
    float w3[64];
    float b3;
};

__device__ void load_mlp_weights(MlpW* s,
                                 const float* w1, const float* b1, const float* g1, const float* be1,
                                 const float* w2, const float* b2, const float* g2, const float* be2,
                                 const float* w3, const float* b3,
                                 int tid, int nthreads) {
    for (int i = tid; i < 16 * 64; i += nthreads) {
        int u = i / 16, k = i % 16;
        s->w1t[k * 64 + u] = w1[i];
    }
    for (int i = tid; i < 64 * 64; i += nthreads) {
        int u = i / 64, k = i % 64;
        s->w2t[k * 64 + u] = w2[i];
    }
    for (int i = tid; i < 64; i += nthreads) {
        s->b1[i] = b1[i];  s->g1[i] = g1[i];  s->be1[i] = be1[i];
        s->b2[i] = b2[i];  s->g2[i] = g2[i];  s->be2[i] = be2[i];
        s->w3[i] = w3[i];
    }
    if (tid == 0) s->b3 = b3[0];
}

__device__ float warp_mlp(const MlpW* W, const float f[16], int lane) {
    float a0 = W->b1[lane], a1 = W->b1[lane + 32];
#pragma unroll
    for (int k = 0; k < 16; k++) {
        a0 = fmaf(f[k], W->w1t[k * 64 + lane], a0);
        a1 = fmaf(f[k], W->w1t[k * 64 + 32 + lane], a1);
    }
    float h0 = gelu(a0), h1 = gelu(a1);
    float mu  = warp_reduce_sum(h0 + h1) * (1.0f / 64.0f);
    float d0 = h0 - mu, d1 = h1 - mu;
    float var = warp_reduce_sum(d0 * d0 + d1 * d1) * (1.0f / 64.0f);
    float inv = 1.0f / sqrtf(var + 1e-5f);
    h0 = d0 * inv * W->g1[lane]      + W->be1[lane];
    h1 = d1 * inv * W->g1[lane + 32] + W->be1[lane + 32];

    a0 = W->b2[lane];
    a1 = W->b2[lane + 32];
#pragma unroll
    for (int k = 0; k < 32; k++) {
        float x0 = __shfl_sync(0xffffffffu, h0, k);
        float x1 = __shfl_sync(0xffffffffu, h1, k);
        a0 = fmaf(x0, W->w2t[k * 64 + lane], a0);
        a0 = fmaf(x1, W->w2t[(k + 32) * 64 + lane], a0);
        a1 = fmaf(x0, W->w2t[k * 64 + 32 + lane], a1);
        a1 = fmaf(x1, W->w2t[(k + 32) * 64 + 32 + lane], a1);
    }
    h0 = gelu(a0); h1 = gelu(a1);
    mu  = warp_reduce_sum(h0 + h1) * (1.0f / 64.0f);
    d0 = h0 - mu; d1 = h1 - mu;
    var = warp_reduce_sum(d0 * d0 + d1 * d1) * (1.0f / 64.0f);
    inv = 1.0f / sqrtf(var + 1e-5f);
    h0 = d0 * inv * W->g2[lane]      + W->be2[lane];
    h1 = d1 * inv * W->g2[lane + 32] + W->be2[lane + 32];

    float out = h0 * W->w3[lane] + h1 * W->w3[lane + 32];
    out = warp_reduce_sum(out) + W->b3;
    return out;
}

// ---------------------------------------------------------------- kernels

__global__ void init_kernel() {
    int i = blockIdx.x * 512 + threadIdx.x;
    if (i < Bdim * UST) g_v[i] = 0.0f;
    if (i < Bdim * Pdim) {
        int b = i >> 3, p = i & 7;
        g_dA[((size_t)b * MP + Mdim) * Pdim + p] = 0.0f;
        g_dB[((size_t)b * MP + Mdim) * Pdim + p] = 0.0f;
    }
}

// Convert scores -> half(S*log2e) row-major AND transposed, 64x64 tiles.
__global__ __launch_bounds__(256) void prep_kernel(const float* __restrict__ scores) {
    __shared__ float tile[64][65];
    int b = blockIdx.z;
    int tr0 = blockIdx.y * 64;   // m tile base
    int tc0 = blockIdx.x * 64;   // n tile base
    int t = threadIdx.x;
    int r = t >> 4;              // 0..15
    int c4 = (t & 15) * 4;       // 0..60

    const float* sp = scores + ((size_t)b * Mdim + tr0) * Ndim + tc0;
    __half* hR = g_hR + ((size_t)b * Mdim + tr0) * Ndim + tc0;
#pragma unroll
    for (int i = 0; i < 4; i++) {
        int row = r + i * 16;
        float4 s = *reinterpret_cast<const float4*>(sp + (size_t)row * Ndim + c4);
        float4 sc;
        sc.x = s.x * LOG2E_; sc.y = s.y * LOG2E_;
        sc.z = s.z * LOG2E_; sc.w = s.w * LOG2E_;
        tile[row][c4 + 0] = sc.x;
        tile[row][c4 + 1] = sc.y;
        tile[row][c4 + 2] = sc.z;
        tile[row][c4 + 3] = sc.w;
        __half2 h01 = __floats2half2_rn(sc.x, sc.y);
        __half2 h23 = __floats2half2_rn(sc.z, sc.w);
        uint2 pk;
        pk.x = *reinterpret_cast<unsigned*>(&h01);
        pk.y = *reinterpret_cast<unsigned*>(&h23);
        *reinterpret_cast<uint2*>(hR + (size_t)row * Ndim + c4) = pk;
    }
    __syncthreads();
    __half* hC = g_hC + ((size_t)b * Ndim + tc0) * Mdim + tr0;
#pragma unroll
    for (int i = 0; i < 4; i++) {
        int row = r + i * 16;    // n within tile
        float x0 = tile[c4 + 0][row];
        float x1 = tile[c4 + 1][row];
        float x2 = tile[c4 + 2][row];
        float x3 = tile[c4 + 3][row];
        __half2 h01 = __floats2half2_rn(x0, x1);
        __half2 h23 = __floats2half2_rn(x2, x3);
        uint2 pk;
        pk.x = *reinterpret_cast<unsigned*>(&h01);
        pk.y = *reinterpret_cast<unsigned*>(&h23);
        *reinterpret_cast<uint2*>(hC + (size_t)row * Mdim + c4) = pk;
    }
}

__global__ __launch_bounds__(256) void proj_kernel(const float* __restrict__ mdesc,
                                                   const float* __restrict__ pw,
                                                   const float* __restrict__ pb,
                                                   int which) {
    __shared__ float sw[Pdim * Ddim];
    __shared__ float sb[Pdim];
    int tid = threadIdx.x, b = blockIdx.y;
    for (int i = tid; i < Pdim * Ddim; i += 256) sw[i] = pw[i];
    if (tid < Pdim) sb[tid] = pb[tid];
    __syncthreads();
    int m = blockIdx.x * 256 + tid;
    float acc[Pdim];
#pragma unroll
    for (int p = 0; p < Pdim; p++) acc[p] = sb[p];
    const float* base = mdesc + (size_t)b * Ddim * Mdim + m;
#pragma unroll 4
    for (int d = 0; d < Ddim; d++) {
        float val = base[(size_t)d * Mdim];
#pragma unroll
        for (int p = 0; p < Pdim; p++) acc[p] = fmaf(val, sw[p * Ddim + d], acc[p]);
    }
    float* dOut = which ? g_dB : g_dA;
    float* o = dOut + ((size_t)b * MP + m) * Pdim;
#pragma unroll
    for (int p = 0; p < Pdim; p++) o[p] = acc[p];
}

// One Sinkhorn half-step over either axis. axis=0: stream hR rows, read g_v,
// write g_u, desc g_dA. axis=1: stream hC rows (= S columns), read g_u, write
// g_v, desc g_dB. Warp per (row|col), 8 warps/block.
__global__ __launch_bounds__(256) void pass_kernel(
    int axis, const float* __restrict__ alpha,
    const float* w1, const float* b1, const float* g1, const float* be1,
    const float* w2, const float* b2, const float* g2, const float* be2,
    const float* w3, const float* b3) {
    __shared__ MlpW W;
    __shared__ __align__(16) float svs[UST];
    int tid = threadIdx.x, b = blockIdx.y;
    const float* vin  = (axis == 0 ? g_v : g_u) + b * UST;
    float*       uout = (axis == 0 ? g_u : g_v) + b * UST;
    const float* dfeat = (axis == 0 ? g_dA : g_dB) + (size_t)b * MP * Pdim;
    const __half* hmat = (axis == 0 ? g_hR : g_hC) + (size_t)b * Mdim * Ndim;

    load_mlp_weights(&W, w1, b1, g1, be1, w2, b2, g2, be2, w3, b3, tid, 256);
    {
        const float4* gv4 = reinterpret_cast<const float4*>(vin);
        float4* sv4w = reinterpret_cast<float4*>(svs);
        for (int i = tid; i < UST / 4; i += 256) sv4w[i] = gv4[i];
    }
    __syncthreads();

    int warp = tid >> 5, lane = tid & 31;
    int m = blockIdx.x * 8 + warp;
    if (m >= MP) return;

    float alphaL = alpha[0] * LOG2E_;
    bool dust = (m == Mdim);
    const uint2* h4 = reinterpret_cast<const uint2*>(hmat + (size_t)m * Ndim);
    const float4* sv4 = reinterpret_cast<const float4*>(svs);

    float s0 = 0.0f, s1 = 0.0f, s2 = 0.0f, s3 = 0.0f;
    float tE[5], tO[5];
#pragma unroll
    for (int i = 0; i < 5; i++) tE[i] = tO[i] = -INFINITY;

    if (!dust) {
#pragma unroll 4
        for (int k = 0; k < 16; k++) {
            int idx = k * 32 + lane;
            uint2 hv = h4[idx];
            float4 vv = sv4[idx];
            float2 fa = __half22float2(*reinterpret_cast<__half2*>(&hv.x));
            float2 fb = __half22float2(*reinterpret_cast<__half2*>(&hv.y));
            float x0 = fa.x + vv.x;
            float x1 = fa.y + vv.y;
            float x2 = fb.x + vv.z;
            float x3 = fb.y + vv.w;
            s0 += ex2(x0); s1 += ex2(x1); s2 += ex2(x2); s3 += ex2(x3);
            ladder5(tE, x0); ladder5(tO, x1);
            ladder5(tE, x2); ladder5(tO, x3);
        }
    } else {
#pragma unroll 4
        for (int k = 0; k < 16; k++) {
            int idx = k * 32 + lane;
            float4 vv = sv4[idx];
            float x0 = alphaL + vv.x;
            float x1 = alphaL + vv.y;
            float x2 = alphaL + vv.z;
            float x3 = alphaL + vv.w;
            s0 += ex2(x0); s1 += ex2(x1); s2 += ex2(x2); s3 += ex2(x3);
            ladder5(tE, x0); ladder5(tO, x1);
            ladder5(tE, x2); ladder5(tO, x3);
        }
    }
    if (lane == 0) {  // dustbin entry at index N
        float x = alphaL + svs[Ndim];
        s0 += ex2(x);
        ladder5(tE, x);
    }

    merge5(tE, tO);
    float tot = warp_reduce_sum((s0 + s1) + (s2 + s3));
    top5_merge_shfl(tE);
    float lse = log2f(tot);

    float l2mu = dust ? -1.0f : -12.0f;  // -log2(4096); dust: log2(2048)-12
    float un = l2mu - lse;

    float f[16];
    f[0] = l2mu * LN2_;
    f[1] = un * LN2_;
    f[2] = 0.0f;
    f[3] = (tE[0] - tE[1]) * LN2_;
    f[4] = (tE[0] - tE[2]) * LN2_;
    f[5] = (tE[0] - tE[3]) * LN2_;
    f[6] = (tE[0] - tE[4]) * LN2_;
    f[7] = (l2mu - un - tE[0]) * LN2_;
    const float* da = dfeat + (size_t)m * Pdim;
#pragma unroll
    for (int p = 0; p < 8; p++) f[8 + p] = da[p];

    float delta = warp_mlp(&W, f, lane);
    if (lane == 0) uout[m] = un + delta * LOG2E_;
}

// Final output: out[b,m,n] = S*log2e + u + v + 12, row-major from fp32 scores.
__global__ __launch_bounds__(256) void out_kernel(const float* __restrict__ scores,
                                                  const float* __restrict__ alpha,
                                                  float* __restrict__ out) {
    __shared__ __align__(16) float svs[UST];
    int tid = threadIdx.x, b = blockIdx.y;
    {
        const float4* gv4 = reinterpret_cast<const float4*>(g_v + b * UST);
        float4* sv4w = reinterpret_cast<float4*>(svs);
        for (int i = tid; i < UST / 4; i += 256) sv4w[i] = gv4[i];
    }
    __syncthreads();
    int warp = tid >> 5, lane = tid & 31;
    int m = blockIdx.x * 8 + warp;
    if (m >= MP) return;
    float alphaL = alpha[0] * LOG2E_;
    float um = g_u[b * UST + m] + 12.0f;
    float* orow = out + ((size_t)b * MP + m) * NP;
    if (m < Mdim) {
        const float4* srow4 = reinterpret_cast<const float4*>(scores + ((size_t)b * Mdim + m) * Ndim);
        const float4* sv4 = reinterpret_cast<const float4*>(svs);
#pragma unroll 4
        for (int k = 0; k < 16; k++) {
            int idx = k * 32 + lane;
            float4 s = srow4[idx];
            float4 vv = sv4[idx];
            int n = idx * 4;
            orow[n + 0] = fmaf(s.x, LOG2E_, um + vv.x);
            orow[n + 1] = fmaf(s.y, LOG2E_, um + vv.y);
            orow[n + 2] = fmaf(s.z, LOG2E_, um + vv.z);
            orow[n + 3] = fmaf(s.w, LOG2E_, um + vv.w);
        }
        if (lane == 0) orow[Ndim] = alphaL + um + svs[Ndim];
    } else {
        for (int k = 0; k < 65; k++) {
            int n = k * 32 + lane;
            if (n < NP) orow[n] = alphaL + um + svs[n];
        }
    }
}

// ---------------------------------------------------------------- launch

extern "C" void kernel_launch(void* const* d_in, const int* in_sizes, int n_in,
                              void* d_out, int out_size) {
    const float* scores = (const float*)d_in[0];
    const float* alpha  = (const float*)d_in[1];
    const float* mdesc0 = (const float*)d_in[2];
    const float* mdesc1 = (const float*)d_in[3];
    const float* pA_w   = (const float*)d_in[4];
    const float* pA_b   = (const float*)d_in[5];
    const float* pB_w   = (const float*)d_in[6];
    const float* pB_b   = (const float*)d_in[7];
    const float* rW[10];
    const float* cW[10];
    for (int i = 0; i < 10; i++) rW[i] = (const float*)d_in[8 + i];
    for (int i = 0; i < 10; i++) cW[i] = (const float*)d_in[18 + i];
    float* out = (float*)d_out;

    init_kernel<<<17, 512>>>();
    prep_kernel<<<dim3(32, 32, Bdim), 256>>>(scores);
    proj_kernel<<<dim3(Mdim / 256, Bdim), 256>>>(mdesc0, pA_w, pA_b, 0);
    proj_kernel<<<dim3(Ndim / 256, Bdim), 256>>>(mdesc1, pB_w, pB_b, 1);

    dim3 pgrid(257, Bdim);  // ceil(2049/8)
    for (int it = 0; it < 3; it++) {
        pass_kernel<<<pgrid, 256>>>(0, alpha,
                                    rW[0], rW[1], rW[2], rW[3], rW[4],
                                    rW[5], rW[6], rW[7], rW[8], rW[9]);
        pass_kernel<<<pgrid, 256>>>(1, alpha,
                                    cW[0], cW[1], cW[2], cW[3], cW[4],
                                    cW[5], cW[6], cW[7], cW[8], cW[9]);
    }
    out_kernel<<<pgrid, 256>>>(scores, alpha, out);
}

// round 6
// speedup vs baseline: 1.3861x; 1.3861x over previous
#include <cuda_runtime.h>
#include <cuda_fp16.h>
#include <math.h>

#define Mdim 2048
#define Ndim 2048
#define MP   2049
#define NP   2049
#define Bdim 4
#define Ddim 256
#define Pdim 8
#define UST  2052   // padded stride for u/v (16B-aligned batch slices)

__device__ float g_u[Bdim * UST];
__device__ float g_v[Bdim * UST];
__device__ float g_dA[(size_t)Bdim * MP * Pdim];
__device__ float g_dB[(size_t)Bdim * MP * Pdim];
__device__ __half g_hC[(size_t)Bdim * Mdim * Ndim];  // half(S^T * log2e)

#define LOG2E_ 1.4426950408889634f
#define LN2_   0.6931471805599453f

// ---------------------------------------------------------------- utilities

__device__ __forceinline__ float ex2(float x) {
    float y;
    asm("ex2.approx.f32 %0, %1;" : "=f"(y) : "f"(x));
    return y;
}

__device__ __forceinline__ float warp_reduce_sum(float x) {
#pragma unroll
    for (int o = 16; o; o >>= 1) x += __shfl_xor_sync(0xffffffffu, x, o);
    return x;
}

__device__ __forceinline__ float gelu(float x) {
    return 0.5f * x * (1.0f + erff(x * 0.7071067811865476f));
}

// fp32 branchless insert into sorted-descending t[5]
__device__ __forceinline__ void ladder5(float t[5], float x) {
#pragma unroll
    for (int i = 0; i < 5; i++) {
        float hi = fmaxf(t[i], x);
        x = fminf(t[i], x);
        t[i] = hi;
    }
}

__device__ __forceinline__ void merge5(float t[5], const float s[5]) {
#pragma unroll
    for (int i = 0; i < 5; i++) ladder5(t, s[i]);
}

__device__ __forceinline__ void top5_merge_shfl(float t[5]) {
#pragma unroll
    for (int o = 16; o; o >>= 1) {
        float p[5];
#pragma unroll
        for (int i = 0; i < 5; i++) p[i] = __shfl_xor_sync(0xffffffffu, t[i], o);
        merge5(t, p);
    }
}

// packed fp16 dual-chain ladder: lo/hi halves are independent chains
__device__ __forceinline__ void ladder2h(__half2 t[5], __half2 x) {
#pragma unroll
    for (int i = 0; i < 5; i++) {
        __half2 hi = __hmax2(t[i], x);
        x = __hmin2(t[i], x);
        t[i] = hi;
    }
}

// ---------------------------------------------------------------- MLP (warp-cooperative)

struct MlpW {
    float w1t[16 * 64];
    float b1[64], g1[64], be1[64];
    float w2t[64 * 64];
    float b2[64], g2[64], be2[64];
    float w3[64];
    float b3;
};

__device__ void load_mlp_weights(MlpW* s,
                                 const float* w1, const float* b1, const float* g1, const float* be1,
                                 const float* w2, const float* b2, const float* g2, const float* be2,
                                 const float* w3, const float* b3,
                                 int tid, int nthreads) {
    for (int i = tid; i < 16 * 64; i += nthreads) {
        int u = i / 16, k = i % 16;
        s->w1t[k * 64 + u] = w1[i];
    }
    for (int i = tid; i < 64 * 64; i += nthreads) {
        int u = i / 64, k = i % 64;
        s->w2t[k * 64 + u] = w2[i];
    }
    for (int i = tid; i < 64; i += nthreads) {
        s->b1[i] = b1[i];  s->g1[i] = g1[i];  s->be1[i] = be1[i];
        s->b2[i] = b2[i];  s->g2[i] = g2[i];  s->be2[i] = be2[i];
        s->w3[i] = w3[i];
    }
    if (tid == 0) s->b3 = b3[0];
}

__device__ float warp_mlp(const MlpW* W, const float f[16], int lane) {
    float a0 = W->b1[lane], a1 = W->b1[lane + 32];
#pragma unroll
    for (int k = 0; k < 16; k++) {
        a0 = fmaf(f[k], W->w1t[k * 64 + lane], a0);
        a1 = fmaf(f[k], W->w1t[k * 64 + 32 + lane], a1);
    }
    float h0 = gelu(a0), h1 = gelu(a1);
    float mu  = warp_reduce_sum(h0 + h1) * (1.0f / 64.0f);
    float d0 = h0 - mu, d1 = h1 - mu;
    float var = warp_reduce_sum(d0 * d0 + d1 * d1) * (1.0f / 64.0f);
    float inv = 1.0f / sqrtf(var + 1e-5f);
    h0 = d0 * inv * W->g1[lane]      + W->be1[lane];
    h1 = d1 * inv * W->g1[lane + 32] + W->be1[lane + 32];

    a0 = W->b2[lane];
    a1 = W->b2[lane + 32];
#pragma unroll
    for (int k = 0; k < 32; k++) {
        float x0 = __shfl_sync(0xffffffffu, h0, k);
        float x1 = __shfl_sync(0xffffffffu, h1, k);
        a0 = fmaf(x0, W->w2t[k * 64 + lane], a0);
        a0 = fmaf(x1, W->w2t[(k + 32) * 64 + lane], a0);
        a1 = fmaf(x0, W->w2t[k * 64 + 32 + lane], a1);
        a1 = fmaf(x1, W->w2t[(k + 32) * 64 + 32 + lane], a1);
    }
    h0 = gelu(a0); h1 = gelu(a1);
    mu  = warp_reduce_sum(h0 + h1) * (1.0f / 64.0f);
    d0 = h0 - mu; d1 = h1 - mu;
    var = warp_reduce_sum(d0 * d0 + d1 * d1) * (1.0f / 64.0f);
    inv = 1.0f / sqrtf(var + 1e-5f);
    h0 = d0 * inv * W->g2[lane]      + W->be2[lane];
    h1 = d1 * inv * W->g2[lane + 32] + W->be2[lane + 32];

    float out = h0 * W->w3[lane] + h1 * W->w3[lane + 32];
    out = warp_reduce_sum(out) + W->b3;
    return out;
}

// Shared epilogue: build features, run MLP, write updated potential.
__device__ void pass_epilogue(const MlpW* W, float tot, float t5[5], bool dust,
                              const float* dfeat, float* uout, int m, int lane) {
    float lse = log2f(tot);
    float l2mu = dust ? -1.0f : -12.0f;
    float un = l2mu - lse;
    float f[16];
    f[0] = l2mu * LN2_;
    f[1] = un * LN2_;
    f[2] = 0.0f;
    f[3] = (t5[0] - t5[1]) * LN2_;
    f[4] = (t5[0] - t5[2]) * LN2_;
    f[5] = (t5[0] - t5[3]) * LN2_;
    f[6] = (t5[0] - t5[4]) * LN2_;
    f[7] = (l2mu - un - t5[0]) * LN2_;
    const float* da = dfeat + (size_t)m * Pdim;
#pragma unroll
    for (int p = 0; p < 8; p++) f[8 + p] = da[p];
    float delta = warp_mlp(W, f, lane);
    if (lane == 0) uout[m] = un + delta * LOG2E_;
}

// ---------------------------------------------------------------- kernels

__global__ void init_kernel() {
    int i = blockIdx.x * 512 + threadIdx.x;
    if (i < Bdim * UST) g_v[i] = 0.0f;
    if (i < Bdim * Pdim) {
        int b = i >> 3, p = i & 7;
        g_dA[((size_t)b * MP + Mdim) * Pdim + p] = 0.0f;
        g_dB[((size_t)b * MP + Mdim) * Pdim + p] = 0.0f;
    }
}

// scores -> half(S^T * log2e), 64x64 tiles.
__global__ __launch_bounds__(256) void prep_kernel(const float* __restrict__ scores) {
    __shared__ float tile[64][65];
    int b = blockIdx.z;
    int tr0 = blockIdx.y * 64;   // m tile base
    int tc0 = blockIdx.x * 64;   // n tile base
    int t = threadIdx.x;
    int r = t >> 4;              // 0..15
    int c4 = (t & 15) * 4;       // 0..60

    const float* sp = scores + ((size_t)b * Mdim + tr0) * Ndim + tc0;
#pragma unroll
    for (int i = 0; i < 4; i++) {
        int row = r + i * 16;
        float4 s = *reinterpret_cast<const float4*>(sp + (size_t)row * Ndim + c4);
        tile[row][c4 + 0] = s.x * LOG2E_;
        tile[row][c4 + 1] = s.y * LOG2E_;
        tile[row][c4 + 2] = s.z * LOG2E_;
        tile[row][c4 + 3] = s.w * LOG2E_;
    }
    __syncthreads();
    __half* hC = g_hC + ((size_t)b * Ndim + tc0) * Mdim + tr0;
#pragma unroll
    for (int i = 0; i < 4; i++) {
        int row = r + i * 16;    // n within tile
        __half2 h01 = __floats2half2_rn(tile[c4 + 0][row], tile[c4 + 1][row]);
        __half2 h23 = __floats2half2_rn(tile[c4 + 2][row], tile[c4 + 3][row]);
        uint2 pk;
        pk.x = *reinterpret_cast<unsigned*>(&h01);
        pk.y = *reinterpret_cast<unsigned*>(&h23);
        *reinterpret_cast<uint2*>(hC + (size_t)row * Mdim + c4) = pk;
    }
}

// dOut[b,m,p] = sum_d mdesc[b,d,m] * pw[p,d] + pb[p]
// block: 512 threads = 64 m-values x 8 d-groups (32 d each). grid (32, Bdim).
__global__ __launch_bounds__(512) void proj_kernel(const float* __restrict__ mdesc,
                                                   const float* __restrict__ pw,
                                                   const float* __restrict__ pb,
                                                   int which) {
    __shared__ float sw[Pdim * Ddim];
    __shared__ float part[8][64][Pdim];
    int tid = threadIdx.x, b = blockIdx.y;
    for (int i = tid; i < Pdim * Ddim; i += 512) sw[i] = pw[i];
    __syncthreads();

    int dg = tid >> 6;        // 0..7
    int ml = tid & 63;        // 0..63
    int m0 = blockIdx.x * 64;
    float acc[Pdim];
#pragma unroll
    for (int p = 0; p < Pdim; p++) acc[p] = 0.0f;
    const float* base = mdesc + (size_t)b * Ddim * Mdim + m0 + ml;
#pragma unroll 4
    for (int dd = 0; dd < 32; dd++) {
        int d = dg * 32 + dd;
        float val = base[(size_t)d * Mdim];
#pragma unroll
        for (int p = 0; p < Pdim; p++) acc[p] = fmaf(val, sw[p * Ddim + d], acc[p]);
    }
#pragma unroll
    for (int p = 0; p < Pdim; p++) part[dg][ml][p] = acc[p];
    __syncthreads();

    // 512 threads = 64 m x 8 p
    int m2 = tid >> 3, p2 = tid & 7;
    float sum = pb[p2];
#pragma unroll
    for (int g = 0; g < 8; g++) sum += part[g][m2][p2];
    float* dOut = which ? g_dB : g_dA;
    dOut[((size_t)b * MP + m0 + m2) * Pdim + p2] = sum;
}

// Row pass: warp per row over fp32 scores; fp32 sum, packed-fp16 dual ladder.
__global__ __launch_bounds__(256) void row_pass(
    const float* __restrict__ scores, const float* __restrict__ alpha,
    const float* w1, const float* b1, const float* g1, const float* be1,
    const float* w2, const float* b2, const float* g2, const float* be2,
    const float* w3, const float* b3) {
    __shared__ MlpW W;
    __shared__ __align__(16) float svs[UST];
    int tid = threadIdx.x, b = blockIdx.y;
    load_mlp_weights(&W, w1, b1, g1, be1, w2, b2, g2, be2, w3, b3, tid, 256);
    {
        const float4* gv4 = reinterpret_cast<const float4*>(g_v + b * UST);
        float4* sv4w = reinterpret_cast<float4*>(svs);
        for (int i = tid; i < UST / 4; i += 256) sv4w[i] = gv4[i];
    }
    __syncthreads();

    int warp = tid >> 5, lane = tid & 31;
    int m = blockIdx.x * 8 + warp;
    if (m >= MP) return;

    float alphaL = alpha[0] * LOG2E_;
    bool dust = (m == Mdim);
    const float4* srow4 = reinterpret_cast<const float4*>(scores + ((size_t)b * Mdim + m) * Ndim);
    const float4* sv4 = reinterpret_cast<const float4*>(svs);

    float s0 = 0.0f, s1 = 0.0f, s2 = 0.0f, s3 = 0.0f;
    __half NEGI = __ushort_as_half((unsigned short)0xFC00);
    __half2 t2[5];
#pragma unroll
    for (int i = 0; i < 5; i++) t2[i] = __halves2half2(NEGI, NEGI);

    if (!dust) {
#pragma unroll 4
        for (int k = 0; k < 16; k++) {
            int idx = k * 32 + lane;
            float4 s = srow4[idx];
            float4 vv = sv4[idx];
            float x0 = fmaf(s.x, LOG2E_, vv.x);
            float x1 = fmaf(s.y, LOG2E_, vv.y);
            float x2 = fmaf(s.z, LOG2E_, vv.z);
            float x3 = fmaf(s.w, LOG2E_, vv.w);
            s0 += ex2(x0); s1 += ex2(x1); s2 += ex2(x2); s3 += ex2(x3);
            ladder2h(t2, __floats2half2_rn(x0, x1));
            ladder2h(t2, __floats2half2_rn(x2, x3));
        }
    } else {
#pragma unroll 4
        for (int k = 0; k < 16; k++) {
            int idx = k * 32 + lane;
            float4 vv = sv4[idx];
            float x0 = alphaL + vv.x;
            float x1 = alphaL + vv.y;
            float x2 = alphaL + vv.z;
            float x3 = alphaL + vv.w;
            s0 += ex2(x0); s1 += ex2(x1); s2 += ex2(x2); s3 += ex2(x3);
            ladder2h(t2, __floats2half2_rn(x0, x1));
            ladder2h(t2, __floats2half2_rn(x2, x3));
        }
    }
    float tE[5], tO[5];
#pragma unroll
    for (int i = 0; i < 5; i++) {
        float2 fp = __half22float2(t2[i]);
        tE[i] = fp.x; tO[i] = fp.y;
    }
    if (lane == 0) {  // dustbin column
        float x = alphaL + svs[Ndim];
        s0 += ex2(x);
        ladder5(tE, x);
    }
    merge5(tE, tO);
    float tot = warp_reduce_sum((s0 + s1) + (s2 + s3));
    top5_merge_shfl(tE);

    pass_epilogue(&W, tot, tE, dust, g_dA + (size_t)b * MP * Pdim,
                  g_u + b * UST, m, lane);
}

// Col pass: identical structure over the transposed half matrix.
__global__ __launch_bounds__(256) void col_pass(
    const float* __restrict__ alpha,
    const float* w1, const float* b1, const float* g1, const float* be1,
    const float* w2, const float* b2, const float* g2, const float* be2,
    const float* w3, const float* b3) {
    __shared__ MlpW W;
    __shared__ __align__(16) float sus[UST];
    int tid = threadIdx.x, b = blockIdx.y;
    load_mlp_weights(&W, w1, b1, g1, be1, w2, b2, g2, be2, w3, b3, tid, 256);
    {
        const float4* gu4 = reinterpret_cast<const float4*>(g_u + b * UST);
        float4* su4w = reinterpret_cast<float4*>(sus);
        for (int i = tid; i < UST / 4; i += 256) su4w[i] = gu4[i];
    }
    __syncthreads();

    int warp = tid >> 5, lane = tid & 31;
    int n = blockIdx.x * 8 + warp;
    if (n >= NP) return;

    float alphaL = alpha[0] * LOG2E_;
    bool dust = (n == Ndim);
    const uint2* hrow = reinterpret_cast<const uint2*>(g_hC + ((size_t)b * Ndim + n) * Mdim);
    const float4* su4 = reinterpret_cast<const float4*>(sus);

    float s0 = 0.0f, s1 = 0.0f, s2 = 0.0f, s3 = 0.0f;
    __half NEGI = __ushort_as_half((unsigned short)0xFC00);
    __half2 t2[5];
#pragma unroll
    for (int i = 0; i < 5; i++) t2[i] = __halves2half2(NEGI, NEGI);

    if (!dust) {
#pragma unroll 4
        for (int k = 0; k < 16; k++) {
            int idx = k * 32 + lane;
            uint2 hv = hrow[idx];
            float4 uu = su4[idx];
            float2 fa = __half22float2(*reinterpret_cast<__half2*>(&hv.x));
            float2 fb = __half22float2(*reinterpret_cast<__half2*>(&hv.y));
            float x0 = fa.x + uu.x;
            float x1 = fa.y + uu.y;
            float x2 = fb.x + uu.z;
            float x3 = fb.y + uu.w;
            s0 += ex2(x0); s1 += ex2(x1); s2 += ex2(x2); s3 += ex2(x3);
            ladder2h(t2, __floats2half2_rn(x0, x1));
            ladder2h(t2, __floats2half2_rn(x2, x3));
        }
    } else {
#pragma unroll 4
        for (int k = 0; k < 16; k++) {
            int idx = k * 32 + lane;
            float4 uu = su4[idx];
            float x0 = alphaL + uu.x;
            float x1 = alphaL + uu.y;
            float x2 = alphaL + uu.z;
            float x3 = alphaL + uu.w;
            s0 += ex2(x0); s1 += ex2(x1); s2 += ex2(x2); s3 += ex2(x3);
            ladder2h(t2, __floats2half2_rn(x0, x1));
            ladder2h(t2, __floats2half2_rn(x2, x3));
        }
    }
    float tE[5], tO[5];
#pragma unroll
    for (int i = 0; i < 5; i++) {
        float2 fp = __half22float2(t2[i]);
        tE[i] = fp.x; tO[i] = fp.y;
    }
    if (lane == 0) {  // dustbin row
        float x = alphaL + sus[Mdim];
        s0 += ex2(x);
        ladder5(tE, x);
    }
    merge5(tE, tO);
    float tot = warp_reduce_sum((s0 + s1) + (s2 + s3));
    top5_merge_shfl(tE);

    pass_epilogue(&W, tot, tE, dust, g_dB + (size_t)b * MP * Pdim,
                  g_v + b * UST, n, lane);
}

// Final output: out[b,m,n] = S*log2e + u + v + 12 from fp32 scores.
__global__ __launch_bounds__(256) void out_kernel(const float* __restrict__ scores,
                                                  const float* __restrict__ alpha,
                                                  float* __restrict__ out) {
    __shared__ __align__(16) float svs[UST];
    int tid = threadIdx.x, b = blockIdx.y;
    {
        const float4* gv4 = reinterpret_cast<const float4*>(g_v + b * UST);
        float4* sv4w = reinterpret_cast<float4*>(svs);
        for (int i = tid; i < UST / 4; i += 256) sv4w[i] = gv4[i];
    }
    __syncthreads();
    int warp = tid >> 5, lane = tid & 31;
    int m = blockIdx.x * 8 + warp;
    if (m >= MP) return;
    float alphaL = alpha[0] * LOG2E_;
    float um = g_u[b * UST + m] + 12.0f;
    float* orow = out + ((size_t)b * MP + m) * NP;
    if (m < Mdim) {
        const float4* srow4 = reinterpret_cast<const float4*>(scores + ((size_t)b * Mdim + m) * Ndim);
        const float4* sv4 = reinterpret_cast<const float4*>(svs);
#pragma unroll 4
        for (int k = 0; k < 16; k++) {
            int idx = k * 32 + lane;
            float4 s = srow4[idx];
            float4 vv = sv4[idx];
            int n = idx * 4;
            orow[n + 0] = fmaf(s.x, LOG2E_, um + vv.x);
            orow[n + 1] = fmaf(s.y, LOG2E_, um + vv.y);
            orow[n + 2] = fmaf(s.z, LOG2E_, um + vv.z);
            orow[n + 3] = fmaf(s.w, LOG2E_, um + vv.w);
        }
        if (lane == 0) orow[Ndim] = alphaL + um + svs[Ndim];
    } else {
        for (int k = 0; k < 65; k++) {
            int n = k * 32 + lane;
            if (n < NP) orow[n] = alphaL + um + svs[n];
        }
    }
}

// ---------------------------------------------------------------- launch

extern "C" void kernel_launch(void* const* d_in, const int* in_sizes, int n_in,
                              void* d_out, int out_size) {
    const float* scores = (const float*)d_in[0];
    const float* alpha  = (const float*)d_in[1];
    const float* mdesc0 = (const float*)d_in[2];
    const float* mdesc1 = (const float*)d_in[3];
    const float* pA_w   = (const float*)d_in[4];
    const float* pA_b   = (const float*)d_in[5];
    const float* pB_w   = (const float*)d_in[6];
    const float* pB_b   = (const float*)d_in[7];
    const float* rW[10];
    const float* cW[10];
    for (int i = 0; i < 10; i++) rW[i] = (const float*)d_in[8 + i];
    for (int i = 0; i < 10; i++) cW[i] = (const float*)d_in[18 + i];
    float* out = (float*)d_out;

    init_kernel<<<17, 512>>>();
    prep_kernel<<<dim3(32, 32, Bdim), 256>>>(scores);
    proj_kernel<<<dim3(32, Bdim), 512>>>(mdesc0, pA_w, pA_b, 0);
    proj_kernel<<<dim3(32, Bdim), 512>>>(mdesc1, pB_w, pB_b, 1);

    dim3 pgrid(257, Bdim);  // ceil(2049/8)
    for (int it = 0; it < 3; it++) {
        row_pass<<<pgrid, 256>>>(scores, alpha,
                                 rW[0], rW[1], rW[2], rW[3], rW[4],
                                 rW[5], rW[6], rW[7], rW[8], rW[9]);
        col_pass<<<pgrid, 256>>>(alpha,
                                 cW[0], cW[1], cW[2], cW[3], cW[4],
                                 cW[5], cW[6], cW[7], cW[8], cW[9]);
    }
    out_kernel<<<pgrid, 256>>>(scores, alpha, out);
}

// round 7
// speedup vs baseline: 1.4651x; 1.0570x over previous
#include <cuda_runtime.h>
#include <cuda_fp16.h>
#include <math.h>

#define Mdim 2048
#define Ndim 2048
#define MP   2049
#define NP   2049
#define Bdim 4
#define Ddim 256
#define Pdim 8
#define UST  2052   // padded stride for u/v (16B-aligned batch slices)

__device__ float g_u[Bdim * UST];
__device__ float g_v[Bdim * UST];
__device__ float g_dA[(size_t)Bdim * MP * Pdim];
__device__ float g_dB[(size_t)Bdim * MP * Pdim];
__device__ __half g_ER[(size_t)Bdim * Mdim * Ndim];  // half(e^S), row-major
__device__ __half g_EC[(size_t)Bdim * Mdim * Ndim];  // half(e^S), transposed

#define LOG2E_ 1.4426950408889634f
#define LN2_   0.6931471805599453f
#define WSCALE 24.0f   // w' = 2^(v+24); corrected exactly in epilogue

// ---------------------------------------------------------------- utilities

__device__ __forceinline__ float ex2(float x) {
    float y;
    asm("ex2.approx.f32 %0, %1;" : "=f"(y) : "f"(x));
    return y;
}

__device__ __forceinline__ float warp_reduce_sum(float x) {
#pragma unroll
    for (int o = 16; o; o >>= 1) x += __shfl_xor_sync(0xffffffffu, x, o);
    return x;
}

__device__ __forceinline__ float gelu(float x) {
    return 0.5f * x * (1.0f + erff(x * 0.7071067811865476f));
}

// branchless insert of x into sorted-descending t[5]
__device__ __forceinline__ void ladder5(float t[5], float x) {
#pragma unroll
    for (int i = 0; i < 5; i++) {
        float hi = fmaxf(t[i], x);
        x = fminf(t[i], x);
        t[i] = hi;
    }
}

__device__ __forceinline__ void merge5(float t[5], const float s[5]) {
#pragma unroll
    for (int i = 0; i < 5; i++) ladder5(t, s[i]);
}

__device__ __forceinline__ void top5_merge_shfl(float t[5]) {
#pragma unroll
    for (int o = 16; o; o >>= 1) {
        float p[5];
#pragma unroll
        for (int i = 0; i < 5; i++) p[i] = __shfl_xor_sync(0xffffffffu, t[i], o);
        merge5(t, p);
    }
}

// ---------------------------------------------------------------- MLP (warp-cooperative)

struct MlpW {
    float w1t[16 * 64];
    float b1[64], g1[64], be1[64];
    float w2t[64 * 64];
    float b2[64], g2[64], be2[64];
    float w3[64];
    float b3;
};

__device__ void load_mlp_weights(MlpW* s,
                                 const float* w1, const float* b1, const float* g1, const float* be1,
                                 const float* w2, const float* b2, const float* g2, const float* be2,
                                 const float* w3, const float* b3,
                                 int tid, int nthreads) {
    for (int i = tid; i < 16 * 64; i += nthreads) {
        int u = i / 16, k = i % 16;
        s->w1t[k * 64 + u] = w1[i];
    }
    for (int i = tid; i < 64 * 64; i += nthreads) {
        int u = i / 64, k = i % 64;
        s->w2t[k * 64 + u] = w2[i];
    }
    for (int i = tid; i < 64; i += nthreads) {
        s->b1[i] = b1[i];  s->g1[i] = g1[i];  s->be1[i] = be1[i];
        s->b2[i] = b2[i];  s->g2[i] = g2[i];  s->be2[i] = be2[i];
        s->w3[i] = w3[i];
    }
    if (tid == 0) s->b3 = b3[0];
}

__device__ float warp_mlp(const MlpW* W, const float f[16], int lane) {
    float a0 = W->b1[lane], a1 = W->b1[lane + 32];
#pragma unroll
    for (int k = 0; k < 16; k++) {
        a0 = fmaf(f[k], W->w1t[k * 64 + lane], a0);
        a1 = fmaf(f[k], W->w1t[k * 64 + 32 + lane], a1);
    }
    float h0 = gelu(a0), h1 = gelu(a1);
    float mu  = warp_reduce_sum(h0 + h1) * (1.0f / 64.0f);
    float d0 = h0 - mu, d1 = h1 - mu;
    float var = warp_reduce_sum(d0 * d0 + d1 * d1) * (1.0f / 64.0f);
    float inv = 1.0f / sqrtf(var + 1e-5f);
    h0 = d0 * inv * W->g1[lane]      + W->be1[lane];
    h1 = d1 * inv * W->g1[lane + 32] + W->be1[lane + 32];

    a0 = W->b2[lane];
    a1 = W->b2[lane + 32];
#pragma unroll
    for (int k = 0; k < 32; k++) {
        float x0 = __shfl_sync(0xffffffffu, h0, k);
        float x1 = __shfl_sync(0xffffffffu, h1, k);
        a0 = fmaf(x0, W->w2t[k * 64 + lane], a0);
        a0 = fmaf(x1, W->w2t[(k + 32) * 64 + lane], a0);
        a1 = fmaf(x0, W->w2t[k * 64 + 32 + lane], a1);
        a1 = fmaf(x1, W->w2t[(k + 32) * 64 + 32 + lane], a1);
    }
    h0 = gelu(a0); h1 = gelu(a1);
    mu  = warp_reduce_sum(h0 + h1) * (1.0f / 64.0f);
    d0 = h0 - mu; d1 = h1 - mu;
    var = warp_reduce_sum(d0 * d0 + d1 * d1) * (1.0f / 64.0f);
    inv = 1.0f / sqrtf(var + 1e-5f);
    h0 = d0 * inv * W->g2[lane]      + W->be2[lane];
    h1 = d1 * inv * W->g2[lane + 32] + W->be2[lane + 32];

    float out = h0 * W->w3[lane] + h1 * W->w3[lane + 32];
    out = warp_reduce_sum(out) + W->b3;
    return out;
}

// ---------------------------------------------------------------- kernels

__global__ void init_kernel() {
    int i = blockIdx.x * 512 + threadIdx.x;
    if (i < Bdim * UST) { g_v[i] = 0.0f; g_u[i] = 0.0f; }
    if (i < Bdim * Pdim) {
        int b = i >> 3, p = i & 7;
        g_dA[((size_t)b * MP + Mdim) * Pdim + p] = 0.0f;
        g_dB[((size_t)b * MP + Mdim) * Pdim + p] = 0.0f;
    }
}

// scores -> half(e^S): row-major (ER) and transposed (EC), 64x64 tiles.
__global__ __launch_bounds__(256) void prep_kernel(const float* __restrict__ scores) {
    __shared__ float tile[64][65];
    int b = blockIdx.z;
    int tr0 = blockIdx.y * 64;   // m tile base
    int tc0 = blockIdx.x * 64;   // n tile base
    int t = threadIdx.x;
    int r = t >> 4;              // 0..15
    int c4 = (t & 15) * 4;       // 0..60

    const float* sp = scores + ((size_t)b * Mdim + tr0) * Ndim + tc0;
    __half* eR = g_ER + ((size_t)b * Mdim + tr0) * Ndim + tc0;
#pragma unroll
    for (int i = 0; i < 4; i++) {
        int row = r + i * 16;
        float4 s = *reinterpret_cast<const float4*>(sp + (size_t)row * Ndim + c4);
        float e0 = ex2(s.x * LOG2E_);
        float e1 = ex2(s.y * LOG2E_);
        float e2 = ex2(s.z * LOG2E_);
        float e3 = ex2(s.w * LOG2E_);
        tile[row][c4 + 0] = e0;
        tile[row][c4 + 1] = e1;
        tile[row][c4 + 2] = e2;
        tile[row][c4 + 3] = e3;
        __half2 h01 = __floats2half2_rn(e0, e1);
        __half2 h23 = __floats2half2_rn(e2, e3);
        uint2 pk;
        pk.x = *reinterpret_cast<unsigned*>(&h01);
        pk.y = *reinterpret_cast<unsigned*>(&h23);
        *reinterpret_cast<uint2*>(eR + (size_t)row * Ndim + c4) = pk;
    }
    __syncthreads();
    __half* eC = g_EC + ((size_t)b * Ndim + tc0) * Mdim + tr0;
#pragma unroll
    for (int i = 0; i < 4; i++) {
        int row = r + i * 16;    // n within tile
        __half2 h01 = __floats2half2_rn(tile[c4 + 0][row], tile[c4 + 1][row]);
        __half2 h23 = __floats2half2_rn(tile[c4 + 2][row], tile[c4 + 3][row]);
        uint2 pk;
        pk.x = *reinterpret_cast<unsigned*>(&h01);
        pk.y = *reinterpret_cast<unsigned*>(&h23);
        *reinterpret_cast<uint2*>(eC + (size_t)row * Mdim + c4) = pk;
    }
}

// dOut[b,m,p] = sum_d mdesc[b,d,m] * pw[p,d] + pb[p]
// 256 threads = 32 m x 8 d-groups; grid (64, Bdim).
__global__ __launch_bounds__(256) void proj_kernel(const float* __restrict__ mdesc,
                                                   const float* __restrict__ pw,
                                                   const float* __restrict__ pb,
                                                   int which) {
    __shared__ float sw[Pdim * Ddim];
    __shared__ float part[8][32][Pdim];
    int tid = threadIdx.x, b = blockIdx.y;
    for (int i = tid; i < Pdim * Ddim; i += 256) sw[i] = pw[i];
    __syncthreads();

    int dg = tid >> 5;        // 0..7
    int ml = tid & 31;        // 0..31
    int m0 = blockIdx.x * 32;
    float acc[Pdim];
#pragma unroll
    for (int p = 0; p < Pdim; p++) acc[p] = 0.0f;
    const float* base = mdesc + (size_t)b * Ddim * Mdim + m0 + ml;
#pragma unroll 4
    for (int dd = 0; dd < 32; dd++) {
        int d = dg * 32 + dd;
        float val = base[(size_t)d * Mdim];
#pragma unroll
        for (int p = 0; p < Pdim; p++) acc[p] = fmaf(val, sw[p * Ddim + d], acc[p]);
    }
#pragma unroll
    for (int p = 0; p < Pdim; p++) part[dg][ml][p] = acc[p];
    __syncthreads();

    int m2 = tid >> 3, p2 = tid & 7;   // 32 m x 8 p
    float sum = pb[p2];
#pragma unroll
    for (int g = 0; g < 8; g++) sum += part[g][m2][p2];
    float* dOut = which ? g_dB : g_dA;
    dOut[((size_t)b * MP + m0 + m2) * Pdim + p2] = sum;
}

// One Sinkhorn half-step. Linear domain: p = E * 2^(v+24).
// axis=0: E=ER, vin=g_v, uout=g_u, desc=g_dA.  axis=1: E=EC, swap.
__global__ __launch_bounds__(256) void sink_pass(
    int axis, const float* __restrict__ alpha,
    const float* w1, const float* b1, const float* g1, const float* be1,
    const float* w2, const float* b2, const float* g2, const float* be2,
    const float* w3, const float* b3) {
    __shared__ MlpW W;
    __shared__ __align__(16) float ws[UST];   // 2^(v+24)
    int tid = threadIdx.x, b = blockIdx.y;
    const float* vin  = (axis == 0 ? g_v : g_u) + b * UST;
    float*       uout = (axis == 0 ? g_u : g_v) + b * UST;
    const float* dfeat = (axis == 0 ? g_dA : g_dB) + (size_t)b * MP * Pdim;
    const __half* Emat = (axis == 0 ? g_ER : g_EC) + (size_t)b * Mdim * Ndim;

    load_mlp_weights(&W, w1, b1, g1, be1, w2, b2, g2, be2, w3, b3, tid, 256);
    for (int i = tid; i < UST; i += 256) ws[i] = ex2(vin[i] + WSCALE);
    __syncthreads();

    int warp = tid >> 5, lane = tid & 31;
    int m = blockIdx.x * 8 + warp;
    if (m >= MP) return;

    float alphaL = alpha[0] * LOG2E_;
    float EA = ex2(alphaL);           // e^alpha
    bool dust = (m == Mdim);
    const uint2* erow = reinterpret_cast<const uint2*>(Emat + (size_t)m * Ndim);
    const float4* ws4 = reinterpret_cast<const float4*>(ws);

    float s0 = 0.0f, s1 = 0.0f, s2 = 0.0f, s3 = 0.0f;
    float t5[5] = {-INFINITY, -INFINITY, -INFINITY, -INFINITY, -INFINITY};

    if (!dust) {
#pragma unroll
        for (int i = 0; i < 8; i++) {
            uint2 ea = erow[i * 64 + lane];
            uint2 eb = erow[i * 64 + 32 + lane];
            float4 wa = ws4[i * 64 + lane];
            float4 wb = ws4[i * 64 + 32 + lane];
            float2 gA = __half22float2(*reinterpret_cast<__half2*>(&ea.x));
            float2 gB = __half22float2(*reinterpret_cast<__half2*>(&ea.y));
            float2 gC = __half22float2(*reinterpret_cast<__half2*>(&eb.x));
            float2 gD = __half22float2(*reinterpret_cast<__half2*>(&eb.y));
            float p0 = gA.x * wa.x, p1 = gA.y * wa.y;
            float p2 = gB.x * wa.z, p3 = gB.y * wa.w;
            float p4 = gC.x * wb.x, p5 = gC.y * wb.y;
            float p6 = gD.x * wb.z, p7 = gD.y * wb.w;
            s0 += p0; s1 += p1; s2 += p2; s3 += p3;
            s0 += p4; s1 += p5; s2 += p6; s3 += p7;
            float gm = fmaxf(fmaxf(fmaxf(p0, p1), fmaxf(p2, p3)),
                             fmaxf(fmaxf(p4, p5), fmaxf(p6, p7)));
            ladder5(t5, gm);
        }
    } else {
#pragma unroll
        for (int i = 0; i < 8; i++) {
            float4 wa = ws4[i * 64 + lane];
            float4 wb = ws4[i * 64 + 32 + lane];
            float p0 = EA * wa.x, p1 = EA * wa.y, p2 = EA * wa.z, p3 = EA * wa.w;
            float p4 = EA * wb.x, p5 = EA * wb.y, p6 = EA * wb.z, p7 = EA * wb.w;
            s0 += p0; s1 += p1; s2 += p2; s3 += p3;
            s0 += p4; s1 += p5; s2 += p6; s3 += p7;
            float gm = fmaxf(fmaxf(fmaxf(p0, p1), fmaxf(p2, p3)),
                             fmaxf(fmaxf(p4, p5), fmaxf(p6, p7)));
            ladder5(t5, gm);
        }
    }
    if (lane == 0) {  // dustbin column
        float p = EA * ws[Ndim];
        s0 += p;
        ladder5(t5, p);
    }

    float tot = warp_reduce_sum((s0 + s1) + (s2 + s3));
    top5_merge_shfl(t5);

    float lse = log2f(tot) - WSCALE;
    float l2mu = dust ? -1.0f : -12.0f;
    float un = l2mu - lse;

    float f[16];
    f[0] = l2mu * LN2_;
    f[1] = un * LN2_;
    f[2] = 0.0f;
    f[3] = __logf(__fdividef(t5[0], t5[1]));
    f[4] = __logf(__fdividef(t5[0], t5[2]));
    f[5] = __logf(__fdividef(t5[0], t5[3]));
    f[6] = __logf(__fdividef(t5[0], t5[4]));
    f[7] = __logf(__fdividef(tot, t5[0]));
    const float* da = dfeat + (size_t)m * Pdim;
#pragma unroll
    for (int p = 0; p < 8; p++) f[8 + p] = da[p];

    float delta = warp_mlp(&W, f, lane);
    if (lane == 0) uout[m] = un + delta * LOG2E_;
}

// Final output: out[b,m,n] = log2(ER) + u + v + 12 (ER is L2-hot).
__global__ __launch_bounds__(256) void out_kernel(const float* __restrict__ alpha,
                                                  float* __restrict__ out) {
    __shared__ __align__(16) float svs[UST];
    int tid = threadIdx.x, b = blockIdx.y;
    {
        const float4* gv4 = reinterpret_cast<const float4*>(g_v + b * UST);
        float4* sv4w = reinterpret_cast<float4*>(svs);
        for (int i = tid; i < UST / 4; i += 256) sv4w[i] = gv4[i];
    }
    __syncthreads();
    int warp = tid >> 5, lane = tid & 31;
    int m = blockIdx.x * 8 + warp;
    if (m >= MP) return;
    float alphaL = alpha[0] * LOG2E_;
    float um = g_u[b * UST + m] + 12.0f;
    float* orow = out + ((size_t)b * MP + m) * NP;
    if (m < Mdim) {
        const uint2* erow = reinterpret_cast<const uint2*>(g_ER + ((size_t)b * Mdim + m) * Ndim);
#pragma unroll 2
        for (int i = 0; i < 8; i++) {
            uint2 ea = erow[i * 64 + lane];
            uint2 eb = erow[i * 64 + 32 + lane];
            float2 gA = __half22float2(*reinterpret_cast<__half2*>(&ea.x));
            float2 gB = __half22float2(*reinterpret_cast<__half2*>(&ea.y));
            float2 gC = __half22float2(*reinterpret_cast<__half2*>(&eb.x));
            float2 gD = __half22float2(*reinterpret_cast<__half2*>(&eb.y));
            int n0 = i * 256 + lane * 4;
            int n1 = n0 + 128;
            orow[n0 + 0] = __log2f(gA.x) + um + svs[n0 + 0];
            orow[n0 + 1] = __log2f(gA.y) + um + svs[n0 + 1];
            orow[n0 + 2] = __log2f(gB.x) + um + svs[n0 + 2];
            orow[n0 + 3] = __log2f(gB.y) + um + svs[n0 + 3];
            orow[n1 + 0] = __log2f(gC.x) + um + svs[n1 + 0];
            orow[n1 + 1] = __log2f(gC.y) + um + svs[n1 + 1];
            orow[n1 + 2] = __log2f(gD.x) + um + svs[n1 + 2];
            orow[n1 + 3] = __log2f(gD.y) + um + svs[n1 + 3];
        }
        if (lane == 0) orow[Ndim] = alphaL + um + svs[Ndim];
    } else {
        for (int k = 0; k < 65; k++) {
            int n = k * 32 + lane;
            if (n < NP) orow[n] = alphaL + um + svs[n];
        }
    }
}

// ---------------------------------------------------------------- launch

extern "C" void kernel_launch(void* const* d_in, const int* in_sizes, int n_in,
                              void* d_out, int out_size) {
    const float* scores = (const float*)d_in[0];
    const float* alpha  = (const float*)d_in[1];
    const float* mdesc0 = (const float*)d_in[2];
    const float* mdesc1 = (const float*)d_in[3];
    const float* pA_w   = (const float*)d_in[4];
    const float* pA_b   = (const float*)d_in[5];
    const float* pB_w   = (const float*)d_in[6];
    const float* pB_b   = (const float*)d_in[7];
    const float* rW[10];
    const float* cW[10];
    for (int i = 0; i < 10; i++) rW[i] = (const float*)d_in[8 + i];
    for (int i = 0; i < 10; i++) cW[i] = (const float*)d_in[18 + i];
    float* out = (float*)d_out;

    init_kernel<<<17, 512>>>();
    prep_kernel<<<dim3(32, 32, Bdim), 256>>>(scores);
    proj_kernel<<<dim3(64, Bdim), 256>>>(mdesc0, pA_w, pA_b, 0);
    proj_kernel<<<dim3(64, Bdim), 256>>>(mdesc1, pB_w, pB_b, 1);

    dim3 pgrid(257, Bdim);  // ceil(2049/8)
    for (int it = 0; it < 3; it++) {
        sink_pass<<<pgrid, 256>>>(0, alpha,
                                  rW[0], rW[1], rW[2], rW[3], rW[4],
                                  rW[5], rW[6], rW[7], rW[8], rW[9]);
        sink_pass<<<pgrid, 256>>>(1, alpha,
                                  cW[0], cW[1], cW[2], cW[3], cW[4],
                                  cW[5], cW[6], cW[7], cW[8], cW[9]);
    }
    out_kernel<<<pgrid, 256>>>(alpha, out);
}

// round 9
// speedup vs baseline: 1.9783x; 1.3503x over previous
#include <cuda_runtime.h>
#include <cuda_fp16.h>
#include <math.h>

#define Mdim 2048
#define Ndim 2048
#define MP   2049
#define NP   2049
#define Bdim 4
#define Ddim 256
#define Pdim 8
#define UST  2052   // padded stride for u/v (16B-aligned batch slices)

__device__ float g_u[Bdim * UST];
__device__ float g_v[Bdim * UST];
__device__ float g_dA[(size_t)Bdim * MP * Pdim];
__device__ float g_dB[(size_t)Bdim * MP * Pdim];
__device__ __half g_ER[(size_t)Bdim * Mdim * Ndim];  // half(e^S), row-major
__device__ __half g_EC[(size_t)Bdim * Mdim * Ndim];  // half(e^S), transposed
__device__ unsigned g_count;                          // grid-barrier counter

#define LOG2E_ 1.4426950408889634f
#define LN2_   0.6931471805599453f
#define WSCALE 24.0f   // w' = 2^(v+24); corrected exactly in epilogue

// ---------------------------------------------------------------- utilities

__device__ __forceinline__ float ex2(float x) {
    float y;
    asm("ex2.approx.f32 %0, %1;" : "=f"(y) : "f"(x));
    return y;
}

__device__ __forceinline__ float warp_reduce_sum(float x) {
#pragma unroll
    for (int o = 16; o; o >>= 1) x += __shfl_xor_sync(0xffffffffu, x, o);
    return x;
}

__device__ __forceinline__ float gelu(float x) {
    return 0.5f * x * (1.0f + erff(x * 0.7071067811865476f));
}

__device__ __forceinline__ void ladder5(float t[5], float x) {
#pragma unroll
    for (int i = 0; i < 5; i++) {
        float hi = fmaxf(t[i], x);
        x = fminf(t[i], x);
        t[i] = hi;
    }
}

__device__ __forceinline__ void merge5(float t[5], const float s[5]) {
#pragma unroll
    for (int i = 0; i < 5; i++) ladder5(t, s[i]);
}

__device__ __forceinline__ void top5_merge_shfl(float t[5]) {
#pragma unroll
    for (int o = 16; o; o >>= 1) {
        float p[5];
#pragma unroll
        for (int i = 0; i < 5; i++) p[i] = __shfl_xor_sync(0xffffffffu, t[i], o);
        merge5(t, p);
    }
}

// ---------------------------------------------------------------- MLP (warp-cooperative)

struct alignas(16) MlpW {
    float w1t[16 * 64];
    float b1[64], g1[64], be1[64];
    float w2t[64 * 64];
    float b2[64], g2[64], be2[64];
    float w3[64];
    float b3;
    float pad[3];   // pad to 16-byte multiple so following members stay aligned
};
static_assert(sizeof(MlpW) % 16 == 0, "MlpW must be 16B multiple");

struct alignas(16) SmemAll {
    MlpW Wr;
    MlpW Wc;
    float ws[UST];
};
static_assert(offsetof(SmemAll, ws) % 16 == 0, "ws must be 16B aligned");

__device__ void load_mlp_weights(MlpW* s,
                                 const float* w1, const float* b1, const float* g1, const float* be1,
                                 const float* w2, const float* b2, const float* g2, const float* be2,
                                 const float* w3, const float* b3,
                                 int tid, int nthreads) {
    for (int i = tid; i < 16 * 64; i += nthreads) {
        int u = i / 16, k = i % 16;
        s->w1t[k * 64 + u] = w1[i];
    }
    for (int i = tid; i < 64 * 64; i += nthreads) {
        int u = i / 64, k = i % 64;
        s->w2t[k * 64 + u] = w2[i];
    }
    for (int i = tid; i < 64; i += nthreads) {
        s->b1[i] = b1[i];  s->g1[i] = g1[i];  s->be1[i] = be1[i];
        s->b2[i] = b2[i];  s->g2[i] = g2[i];  s->be2[i] = be2[i];
        s->w3[i] = w3[i];
    }
    if (tid == 0) s->b3 = b3[0];
}

__device__ float warp_mlp(const MlpW* W, const float f[16], int lane) {
    float a0 = W->b1[lane], a1 = W->b1[lane + 32];
#pragma unroll
    for (int k = 0; k < 16; k++) {
        a0 = fmaf(f[k], W->w1t[k * 64 + lane], a0);
        a1 = fmaf(f[k], W->w1t[k * 64 + 32 + lane], a1);
    }
    float h0 = gelu(a0), h1 = gelu(a1);
    float mu  = warp_reduce_sum(h0 + h1) * (1.0f / 64.0f);
    float d0 = h0 - mu, d1 = h1 - mu;
    float var = warp_reduce_sum(d0 * d0 + d1 * d1) * (1.0f / 64.0f);
    float inv = 1.0f / sqrtf(var + 1e-5f);
    h0 = d0 * inv * W->g1[lane]      + W->be1[lane];
    h1 = d1 * inv * W->g1[lane + 32] + W->be1[lane + 32];

    a0 = W->b2[lane];
    a1 = W->b2[lane + 32];
#pragma unroll
    for (int k = 0; k < 32; k++) {
        float x0 = __shfl_sync(0xffffffffu, h0, k);
        float x1 = __shfl_sync(0xffffffffu, h1, k);
        a0 = fmaf(x0, W->w2t[k * 64 + lane], a0);
        a0 = fmaf(x1, W->w2t[(k + 32) * 64 + lane], a0);
        a1 = fmaf(x0, W->w2t[k * 64 + 32 + lane], a1);
        a1 = fmaf(x1, W->w2t[(k + 32) * 64 + 32 + lane], a1);
    }
    h0 = gelu(a0); h1 = gelu(a1);
    mu  = warp_reduce_sum(h0 + h1) * (1.0f / 64.0f);
    d0 = h0 - mu; d1 = h1 - mu;
    var = warp_reduce_sum(d0 * d0 + d1 * d1) * (1.0f / 64.0f);
    inv = 1.0f / sqrtf(var + 1e-5f);
    h0 = d0 * inv * W->g2[lane]      + W->be2[lane];
    h1 = d1 * inv * W->g2[lane + 32] + W->be2[lane + 32];

    float out = h0 * W->w3[lane] + h1 * W->w3[lane + 32];
    out = warp_reduce_sum(out) + W->b3;
    return out;
}

// software grid barrier #k (k = 0..): waits until all gridDim.x blocks arrived
__device__ __forceinline__ void grid_barrier(int k) {
    __syncthreads();
    if (threadIdx.x == 0) {
        __threadfence();
        atomicAdd(&g_count, 1u);
        unsigned target = (unsigned)(k + 1) * gridDim.x;
        while (*((volatile unsigned*)&g_count) < target) { __nanosleep(64); }
        __threadfence();
    }
    __syncthreads();
}

// ---------------------------------------------------------------- prologue kernels

__global__ void init_kernel() {
    int i = blockIdx.x * 512 + threadIdx.x;
    if (i == 0) g_count = 0u;
    if (i < Bdim * UST) { g_v[i] = 0.0f; g_u[i] = 0.0f; }
    if (i < Bdim * Pdim) {
        int b = i >> 3, p = i & 7;
        g_dA[((size_t)b * MP + Mdim) * Pdim + p] = 0.0f;
        g_dB[((size_t)b * MP + Mdim) * Pdim + p] = 0.0f;
    }
}

// scores -> half(e^S): row-major (ER) and transposed (EC), 64x64 tiles.
__global__ __launch_bounds__(256) void prep_kernel(const float* __restrict__ scores) {
    __shared__ float tile[64][65];
    int b = blockIdx.z;
    int tr0 = blockIdx.y * 64;
    int tc0 = blockIdx.x * 64;
    int t = threadIdx.x;
    int r = t >> 4;
    int c4 = (t & 15) * 4;

    const float* sp = scores + ((size_t)b * Mdim + tr0) * Ndim + tc0;
    __half* eR = g_ER + ((size_t)b * Mdim + tr0) * Ndim + tc0;
#pragma unroll
    for (int i = 0; i < 4; i++) {
        int row = r + i * 16;
        float4 s = *reinterpret_cast<const float4*>(sp + (size_t)row * Ndim + c4);
        float e0 = ex2(s.x * LOG2E_);
        float e1 = ex2(s.y * LOG2E_);
        float e2 = ex2(s.z * LOG2E_);
        float e3 = ex2(s.w * LOG2E_);
        tile[row][c4 + 0] = e0;
        tile[row][c4 + 1] = e1;
        tile[row][c4 + 2] = e2;
        tile[row][c4 + 3] = e3;
        __half2 h01 = __floats2half2_rn(e0, e1);
        __half2 h23 = __floats2half2_rn(e2, e3);
        uint2 pk;
        pk.x = *reinterpret_cast<unsigned*>(&h01);
        pk.y = *reinterpret_cast<unsigned*>(&h23);
        *reinterpret_cast<uint2*>(eR + (size_t)row * Ndim + c4) = pk;
    }
    __syncthreads();
    __half* eC = g_EC + ((size_t)b * Ndim + tc0) * Mdim + tr0;
#pragma unroll
    for (int i = 0; i < 4; i++) {
        int row = r + i * 16;
        __half2 h01 = __floats2half2_rn(tile[c4 + 0][row], tile[c4 + 1][row]);
        __half2 h23 = __floats2half2_rn(tile[c4 + 2][row], tile[c4 + 3][row]);
        uint2 pk;
        pk.x = *reinterpret_cast<unsigned*>(&h01);
        pk.y = *reinterpret_cast<unsigned*>(&h23);
        *reinterpret_cast<uint2*>(eC + (size_t)row * Mdim + c4) = pk;
    }
}

// dOut[b,m,p] = sum_d mdesc[b,d,m] * pw[p,d] + pb[p]
// 512 threads = 64 m x 8 d-groups; grid (32, Bdim).
__global__ __launch_bounds__(512) void proj_kernel(const float* __restrict__ mdesc,
                                                   const float* __restrict__ pw,
                                                   const float* __restrict__ pb,
                                                   int which) {
    __shared__ float sw[Pdim * Ddim];
    __shared__ float part[8][64][Pdim];
    int tid = threadIdx.x, b = blockIdx.y;
    for (int i = tid; i < Pdim * Ddim; i += 512) sw[i] = pw[i];
    __syncthreads();

    int dg = tid >> 6;
    int ml = tid & 63;
    int m0 = blockIdx.x * 64;
    float acc[Pdim];
#pragma unroll
    for (int p = 0; p < Pdim; p++) acc[p] = 0.0f;
    const float* base = mdesc + (size_t)b * Ddim * Mdim + m0 + ml;
#pragma unroll 4
    for (int dd = 0; dd < 32; dd++) {
        int d = dg * 32 + dd;
        float val = base[(size_t)d * Mdim];
#pragma unroll
        for (int p = 0; p < Pdim; p++) acc[p] = fmaf(val, sw[p * Ddim + d], acc[p]);
    }
#pragma unroll
    for (int p = 0; p < Pdim; p++) part[dg][ml][p] = acc[p];
    __syncthreads();

    int m2 = tid >> 3, p2 = tid & 7;
    float sum = pb[p2];
#pragma unroll
    for (int g = 0; g < 8; g++) sum += part[g][m2][p2];
    float* dOut = which ? g_dB : g_dA;
    dOut[((size_t)b * MP + m0 + m2) * Pdim + p2] = sum;
}

// ---------------------------------------------------------------- persistent Sinkhorn

// one row's sweep + MLP update (linear domain)
__device__ void row_work(const MlpW* W, const __half* Emat, const float* ws,
                         float EA, const float* dfeat, float* uout,
                         int m, int lane) {
    bool dust = (m == Mdim);
    const uint2* erow = reinterpret_cast<const uint2*>(Emat + (size_t)m * Ndim);
    const float4* ws4 = reinterpret_cast<const float4*>(ws);

    float s0 = 0.0f, s1 = 0.0f, s2 = 0.0f, s3 = 0.0f;
    float t5[5] = {-INFINITY, -INFINITY, -INFINITY, -INFINITY, -INFINITY};

    if (!dust) {
#pragma unroll
        for (int i = 0; i < 8; i++) {
            uint2 ea = erow[i * 64 + lane];
            uint2 eb = erow[i * 64 + 32 + lane];
            float4 wa = ws4[i * 64 + lane];
            float4 wb = ws4[i * 64 + 32 + lane];
            float2 gA = __half22float2(*reinterpret_cast<__half2*>(&ea.x));
            float2 gB = __half22float2(*reinterpret_cast<__half2*>(&ea.y));
            float2 gC = __half22float2(*reinterpret_cast<__half2*>(&eb.x));
            float2 gD = __half22float2(*reinterpret_cast<__half2*>(&eb.y));
            float p0 = gA.x * wa.x, p1 = gA.y * wa.y;
            float p2 = gB.x * wa.z, p3 = gB.y * wa.w;
            float p4 = gC.x * wb.x, p5 = gC.y * wb.y;
            float p6 = gD.x * wb.z, p7 = gD.y * wb.w;
            s0 += p0; s1 += p1; s2 += p2; s3 += p3;
            s0 += p4; s1 += p5; s2 += p6; s3 += p7;
            float gm = fmaxf(fmaxf(fmaxf(p0, p1), fmaxf(p2, p3)),
                             fmaxf(fmaxf(p4, p5), fmaxf(p6, p7)));
            ladder5(t5, gm);
        }
    } else {
#pragma unroll
        for (int i = 0; i < 8; i++) {
            float4 wa = ws4[i * 64 + lane];
            float4 wb = ws4[i * 64 + 32 + lane];
            float p0 = EA * wa.x, p1 = EA * wa.y, p2 = EA * wa.z, p3 = EA * wa.w;
            float p4 = EA * wb.x, p5 = EA * wb.y, p6 = EA * wb.z, p7 = EA * wb.w;
            s0 += p0; s1 += p1; s2 += p2; s3 += p3;
            s0 += p4; s1 += p5; s2 += p6; s3 += p7;
            float gm = fmaxf(fmaxf(fmaxf(p0, p1), fmaxf(p2, p3)),
                             fmaxf(fmaxf(p4, p5), fmaxf(p6, p7)));
            ladder5(t5, gm);
        }
    }
    if (lane == 0) {
        float p = EA * ws[Ndim];
        s0 += p;
        ladder5(t5, p);
    }

    float tot = warp_reduce_sum((s0 + s1) + (s2 + s3));
    top5_merge_shfl(t5);

    float lse = log2f(tot) - WSCALE;
    float l2mu = dust ? -1.0f : -12.0f;
    float un = l2mu - lse;

    float f[16];
    f[0] = l2mu * LN2_;
    f[1] = un * LN2_;
    f[2] = 0.0f;
    f[3] = __logf(__fdividef(t5[0], t5[1]));
    f[4] = __logf(__fdividef(t5[0], t5[2]));
    f[5] = __logf(__fdividef(t5[0], t5[3]));
    f[6] = __logf(__fdividef(t5[0], t5[4]));
    f[7] = __logf(__fdividef(tot, t5[0]));
    const float* da = dfeat + (size_t)m * Pdim;
#pragma unroll
    for (int p = 0; p < 8; p++) f[8 + p] = da[p];

    float delta = warp_mlp(W, f, lane);
    if (lane == 0) uout[m] = un + delta * LOG2E_;
}

__global__ __launch_bounds__(256) void sink_all(
    const float* __restrict__ alpha,
    const float* rw1, const float* rb1, const float* rg1, const float* rbe1,
    const float* rw2, const float* rb2, const float* rg2, const float* rbe2,
    const float* rw3, const float* rb3,
    const float* cw1, const float* cb1, const float* cg1, const float* cbe1,
    const float* cw2, const float* cb2, const float* cg2, const float* cbe2,
    const float* cw3, const float* cb3,
    float* __restrict__ out) {
    extern __shared__ __align__(16) unsigned char smem_raw[];
    SmemAll* S = reinterpret_cast<SmemAll*>(smem_raw);

    int tid = threadIdx.x;
    int warp = tid >> 5, lane = tid & 31;
    int b = blockIdx.x & 3;          // batch bound to block
    int blk = blockIdx.x >> 2;       // block index within batch
    int nb = gridDim.x >> 2;         // blocks per batch

    load_mlp_weights(&S->Wr, rw1, rb1, rg1, rbe1, rw2, rb2, rg2, rbe2, rw3, rb3, tid, 256);
    load_mlp_weights(&S->Wc, cw1, cb1, cg1, cbe1, cw2, cb2, cg2, cbe2, cw3, cb3, tid, 256);

    float alphaL = alpha[0] * LOG2E_;
    float EA = ex2(alphaL);

    int bar = 0;
    for (int it = 0; it < 3; it++) {
#pragma unroll
        for (int axis = 0; axis < 2; axis++) {
            if (it != 0 || axis != 0) grid_barrier(bar++);
            const float* vin  = (axis == 0 ? g_v : g_u) + b * UST;
            float*       uout = (axis == 0 ? g_u : g_v) + b * UST;
            const float* dfeat = (axis == 0 ? g_dA : g_dB) + (size_t)b * MP * Pdim;
            const __half* Emat = (axis == 0 ? g_ER : g_EC) + (size_t)b * Mdim * Ndim;
            const MlpW* W = (axis == 0) ? &S->Wr : &S->Wc;

            for (int i = tid; i < UST; i += 256) S->ws[i] = ex2(vin[i] + WSCALE);
            __syncthreads();

            for (int m = blk * 8 + warp; m < MP; m += nb * 8)
                row_work(W, Emat, S->ws, EA, dfeat, uout, m, lane);
        }
    }

    // ---- output phase ----
    grid_barrier(bar++);
    for (int i = tid; i < UST; i += 256) S->ws[i] = g_v[b * UST + i];  // raw v
    __syncthreads();
    const float* sv = S->ws;

    for (int m = blk * 8 + warp; m < MP; m += nb * 8) {
        float um = g_u[b * UST + m] + 12.0f;
        float* orow = out + ((size_t)b * MP + m) * NP;
        if (m < Mdim) {
            const uint2* erow = reinterpret_cast<const uint2*>(g_ER + ((size_t)b * Mdim + m) * Ndim);
#pragma unroll 2
            for (int i = 0; i < 8; i++) {
                uint2 ea = erow[i * 64 + lane];
                uint2 eb = erow[i * 64 + 32 + lane];
                float2 gA = __half22float2(*reinterpret_cast<__half2*>(&ea.x));
                float2 gB = __half22float2(*reinterpret_cast<__half2*>(&ea.y));
                float2 gC = __half22float2(*reinterpret_cast<__half2*>(&eb.x));
                float2 gD = __half22float2(*reinterpret_cast<__half2*>(&eb.y));
                int n0 = i * 256 + lane * 4;
                int n1 = n0 + 128;
                orow[n0 + 0] = __log2f(gA.x) + um + sv[n0 + 0];
                orow[n0 + 1] = __log2f(gA.y) + um + sv[n0 + 1];
                orow[n0 + 2] = __log2f(gB.x) + um + sv[n0 + 2];
                orow[n0 + 3] = __log2f(gB.y) + um + sv[n0 + 3];
                orow[n1 + 0] = __log2f(gC.x) + um + sv[n1 + 0];
                orow[n1 + 1] = __log2f(gC.y) + um + sv[n1 + 1];
                orow[n1 + 2] = __log2f(gD.x) + um + sv[n1 + 2];
                orow[n1 + 3] = __log2f(gD.y) + um + sv[n1 + 3];
            }
            if (lane == 0) orow[Ndim] = alphaL + um + sv[Ndim];
        } else {
            for (int k = 0; k < 65; k++) {
                int n = k * 32 + lane;
                if (n < NP) orow[n] = alphaL + um + sv[n];
            }
        }
    }
}

// ---------------------------------------------------------------- launch

extern "C" void kernel_launch(void* const* d_in, const int* in_sizes, int n_in,
                              void* d_out, int out_size) {
    const float* scores = (const float*)d_in[0];
    const float* alpha  = (const float*)d_in[1];
    const float* mdesc0 = (const float*)d_in[2];
    const float* mdesc1 = (const float*)d_in[3];
    const float* pA_w   = (const float*)d_in[4];
    const float* pA_b   = (const float*)d_in[5];
    const float* pB_w   = (const float*)d_in[6];
    const float* pB_b   = (const float*)d_in[7];
    const float* rW[10];
    const float* cW[10];
    for (int i = 0; i < 10; i++) rW[i] = (const float*)d_in[8 + i];
    for (int i = 0; i < 10; i++) cW[i] = (const float*)d_in[18 + i];
    float* out = (float*)d_out;

    init_kernel<<<17, 512>>>();
    prep_kernel<<<dim3(32, 32, Bdim), 256>>>(scores);
    proj_kernel<<<dim3(32, Bdim), 512>>>(mdesc0, pA_w, pA_b, 0);
    proj_kernel<<<dim3(32, Bdim), 512>>>(mdesc1, pB_w, pB_b, 1);

    int smem_bytes = (int)sizeof(SmemAll);
    cudaFuncSetAttribute(sink_all, cudaFuncAttributeMaxDynamicSharedMemorySize, smem_bytes);
    int occ = 0;
    cudaOccupancyMaxActiveBlocksPerMultiprocessor(&occ, sink_all, 256, smem_bytes);
    if (occ < 1) occ = 1;
    int smcount = 0;
    cudaDeviceGetAttribute(&smcount, cudaDevAttrMultiProcessorCount, 0);
    if (smcount < 1) smcount = 148;
    int grid = (smcount * occ / 4) * 4;
    if (grid < 4) grid = 4;

    sink_all<<<grid, 256, smem_bytes>>>(alpha,
        rW[0], rW[1], rW[2], rW[3], rW[4], rW[5], rW[6], rW[7], rW[8], rW[9],
        cW[0], cW[1], cW[2], cW[3], cW[4], cW[5], cW[6], cW[7], cW[8], cW[9],
        out);
}